// round 2
// baseline (speedup 1.0000x reference)
#include <cuda_runtime.h>
#include <cstdint>

#define BB 4
#define HH 16
#define SS_ 2048
#define DD 64
#define BQ 64
#define BK 64
#define NT 256
#define NKT (SS_/BK)
#define KT_STRIDE 68
#define SROW 65

typedef unsigned long long u64;

// scratch: per-(b,h) column sums of V  (A3)
__device__ float g_vsum[BB*HH*DD];

__device__ __forceinline__ u64 pack2(float lo, float hi) {
    u64 r; asm("mov.b64 %0, {%1,%2};" : "=l"(r) : "f"(lo), "f"(hi)); return r;
}
__device__ __forceinline__ float2 unpack2(u64 a) {
    float lo, hi; asm("mov.b64 {%0,%1}, %2;" : "=f"(lo), "=f"(hi) : "l"(a));
    return make_float2(lo, hi);
}
// packed 2xfp32 FMA (FFMA2) — 2x throughput vs FFMA-3reg on sm_103a
__device__ __forceinline__ u64 fma2(u64 a, u64 b, u64 c) {
    u64 d; asm("fma.rn.f32x2 %0, %1, %2, %3;" : "=l"(d) : "l"(a), "l"(b), "l"(c));
    return d;
}

// ---------------------------------------------------------------------------
// Kernel 1: g_vsum[bh][d] = sum_k V[bh][k][d]
// ---------------------------------------------------------------------------
__global__ void vsum_kernel(const float* __restrict__ v) {
    int bh = blockIdx.x;
    int tid = threadIdx.x;
    int d = tid & 63, strip = tid >> 6;
    const float* vp = v + (size_t)bh * SS_ * DD;
    float acc = 0.f;
    for (int k = strip; k < SS_; k += 4) acc += vp[k*DD + d];
    __shared__ float red[4][64];
    red[strip][d] = acc;
    __syncthreads();
    if (strip == 0)
        g_vsum[bh*DD + d] = red[0][d] + red[1][d] + red[2][d] + red[3][d];
}

// ---------------------------------------------------------------------------
// Kernel 2: fused attention
//   out = (A1 - lse*A2) - 1e9*(A3 - A2)
//   A1 = sum_k m*s*v, A2 = sum_k m*v, lse = log sum_k exp(s)   (s = qk/8)
// ---------------------------------------------------------------------------
__global__ void __launch_bounds__(NT, 2)
attn_kernel(const float* __restrict__ gq, const float* __restrict__ gk,
            const float* __restrict__ gv, const int* __restrict__ gmask,
            float* __restrict__ gout)
{
    extern __shared__ float smf[];
    float* Qs = smf;                     // BQ x DD          (stride 64)
    float* Kt = Qs + BQ*DD;              // DD x KT_STRIDE   (K transposed)
    float* Vs = Kt + DD*KT_STRIDE;       // BK x DD          (stride 64)
    float* Ss = Vs + BK*DD;              // BQ x SROW
    float* Ms = Ss + BQ*SROW;            // BQ x SROW        (mask as 0/1 float)
    __shared__ float lred[4][BQ];

    const int tid = threadIdx.x;
    const int bid = blockIdx.x;
    const int bh = bid >> 5;             // 64 (b,h) pairs
    const int qt = bid & 31;             // 32 q-tiles
    const int qbase = qt * BQ;

    const float* qp = gq + ((size_t)bh*SS_ + qbase)*DD;
    const float* kp = gk + (size_t)bh*SS_*DD;
    const float* vp = gv + (size_t)bh*SS_*DD;

    // load Q tile (layout-identical copy)
    {
        const float4* src = (const float4*)qp;
        float4* dst = (float4*)Qs;
        #pragma unroll
        for (int i = 0; i < (BQ*DD/4)/NT; i++)
            dst[tid + i*NT] = src[tid + i*NT];
    }

    // persistent accumulators: A1/A2 for (q = tid&63, d in [seg*16, seg*16+16))
    u64 A1[8], A2[8];
    #pragma unroll
    for (int i = 0; i < 8; i++) { A1[i] = 0ull; A2[i] = 0ull; }
    float l_part = 0.f;

    const int tk = tid & 15, tq = tid >> 4;     // phase A mapping
    const int q  = tid & 63, seg = tid >> 6;    // phase B/C mapping
    const int d0 = seg * 16;
    const int kk0 = seg * 16;

    for (int kt2 = 0; kt2 < NKT; kt2++) {
        __syncthreads();   // previous phase C done before overwriting tiles

        // --- load K (transposed), V, mask tile ---
        const float* kptr = kp + (size_t)kt2*BK*DD;
        #pragma unroll
        for (int i = 0; i < (BK*DD)/NT; i++) {
            int idx = tid + i*NT;
            int kk = idx >> 6, dd = idx & 63;
            Kt[dd*KT_STRIDE + kk] = kptr[idx];
        }
        {
            const float4* src = (const float4*)(vp + (size_t)kt2*BK*DD);
            float4* dst = (float4*)Vs;
            #pragma unroll
            for (int i = 0; i < (BK*DD/4)/NT; i++)
                dst[tid + i*NT] = src[tid + i*NT];
        }
        const int* mptr = gmask + (size_t)qbase*SS_ + (size_t)kt2*BK;
        #pragma unroll
        for (int i = 0; i < (BQ*BK)/NT; i++) {
            int idx = tid + i*NT;
            int qq = idx >> 6, kk = idx & 63;
            Ms[qq*SROW + kk] = (mptr[(size_t)qq*SS_ + kk] != 0) ? 1.0f : 0.0f;
        }
        __syncthreads();

        // --- phase A: S = Q K^T * 0.125 (each thread: 4q x 4k, FFMA2 over k) ---
        {
            u64 acc[4][2];
            #pragma unroll
            for (int i = 0; i < 4; i++) { acc[i][0] = 0ull; acc[i][1] = 0ull; }
            #pragma unroll 8
            for (int dd = 0; dd < DD; dd++) {
                float4 bv = *(const float4*)&Kt[dd*KT_STRIDE + 4*tk];
                u64 b01 = pack2(bv.x, bv.y);
                u64 b23 = pack2(bv.z, bv.w);
                #pragma unroll
                for (int iq = 0; iq < 4; iq++) {
                    float a = Qs[(4*tq + iq)*DD + dd];
                    u64 aa = pack2(a, a);
                    acc[iq][0] = fma2(aa, b01, acc[iq][0]);
                    acc[iq][1] = fma2(aa, b23, acc[iq][1]);
                }
            }
            #pragma unroll
            for (int iq = 0; iq < 4; iq++) {
                float2 f0 = unpack2(acc[iq][0]);
                float2 f1 = unpack2(acc[iq][1]);
                float* srow = &Ss[(4*tq + iq)*SROW + 4*tk];
                srow[0] = f0.x*0.125f; srow[1] = f0.y*0.125f;
                srow[2] = f1.x*0.125f; srow[3] = f1.y*0.125f;
            }
        }
        __syncthreads();

        // --- phase B: lse partial (pre-mask scores; no max shift needed,
        //     s ~ N(0,1) so exp is safely in range) ---
        {
            const float* srow = &Ss[q*SROW + kk0];
            #pragma unroll
            for (int i = 0; i < 16; i++) l_part += __expf(srow[i]);
        }

        // --- phase C: A1 += (m*s) @ V, A2 += m @ V  (FFMA2, V broadcast) ---
        {
            const float* srow = &Ss[q*SROW];
            const float* mrow = &Ms[q*SROW];
            #pragma unroll 4
            for (int kk = 0; kk < BK; kk++) {
                float mf = mrow[kk];
                float sc = srow[kk];
                float sm_ = sc * mf;
                u64 mm  = pack2(mf, mf);
                u64 ss2 = pack2(sm_, sm_);
                const ulonglong2* vrow = (const ulonglong2*)&Vs[kk*DD + d0];
                #pragma unroll
                for (int p = 0; p < 4; p++) {
                    ulonglong2 vv = vrow[p];
                    A1[2*p]   = fma2(ss2, vv.x, A1[2*p]);
                    A2[2*p]   = fma2(mm,  vv.x, A2[2*p]);
                    A1[2*p+1] = fma2(ss2, vv.y, A1[2*p+1]);
                    A2[2*p+1] = fma2(mm,  vv.y, A2[2*p+1]);
                }
            }
        }
    }

    // --- lse reduction across the 4 k-segments ---
    lred[seg][q] = l_part;
    __syncthreads();
    float lse = __logf(lred[0][q] + lred[1][q] + lred[2][q] + lred[3][q]);

    // --- epilogue: out = (A1 - lse*A2) - 1e9*(A3 - A2) ---
    const int b = bh >> 4, h = bh & 15;
    float* op = gout + ((size_t)b*SS_ + qbase + q)*(HH*DD) + h*DD + d0;
    const float* vsp = &g_vsum[bh*DD + d0];
    #pragma unroll
    for (int p = 0; p < 8; p++) {
        float2 a1 = unpack2(A1[p]);
        float2 a2 = unpack2(A2[p]);
        float vs0 = vsp[2*p], vs1 = vsp[2*p + 1];
        op[2*p]     = (a1.x - lse*a2.x) - 1e9f*(vs0 - a2.x);
        op[2*p + 1] = (a1.y - lse*a2.y) - 1e9f*(vs1 - a2.y);
    }
}

// ---------------------------------------------------------------------------
extern "C" void kernel_launch(void* const* d_in, const int* in_sizes, int n_in,
                              void* d_out, int out_size) {
    const float* q    = (const float*)d_in[0];
    const float* k    = (const float*)d_in[1];
    const float* v    = (const float*)d_in[2];
    const int*   mask = (const int*)d_in[3];
    float* out = (float*)d_out;

    const int smem_bytes = (BQ*DD + DD*KT_STRIDE + BK*DD + 2*BQ*SROW) * 4; // 83456
    cudaFuncSetAttribute(attn_kernel,
                         cudaFuncAttributeMaxDynamicSharedMemorySize, smem_bytes);

    vsum_kernel<<<BB*HH, 256>>>(v);
    attn_kernel<<<BB*HH*(SS_/BQ), NT, smem_bytes>>>(q, k, v, mask, out);
}

// round 4
// speedup vs baseline: 3.0866x; 3.0866x over previous
#include <cuda_runtime.h>
#include <cstdint>

#define BB 4
#define HH 16
#define SS_ 2048
#define DD 64
#define BQ 128
#define BK 64
#define NKT (SS_/BK)     /* 32 */
#define NBH (BB*HH)      /* 64 */
#define NT 256
#define KSTR 68          /* float stride: conflict-free fragment access */

__device__ float    g_vsum[NBH*DD];
__device__ uint32_t g_mbits[SS_*(SS_/32)];   /* bit-packed mask, shared across bh */

// ---------------- helpers ----------------
__device__ __forceinline__ uint32_t to_tf32(float f) {
    uint32_t r; asm("cvt.rn.tf32.f32 %0, %1;" : "=r"(r) : "f"(f)); return r;
}

// D += A(tf32 m16k8) * B(tf32 k8n8), fp32 accum
__device__ __forceinline__ void mma8(float* d, const uint32_t* a,
                                     uint32_t b0, uint32_t b1) {
    asm volatile(
        "mma.sync.aligned.m16n8k8.row.col.f32.tf32.tf32.f32 "
        "{%0,%1,%2,%3}, {%4,%5,%6,%7}, {%8,%9}, {%0,%1,%2,%3};"
        : "+f"(d[0]), "+f"(d[1]), "+f"(d[2]), "+f"(d[3])
        : "r"(a[0]), "r"(a[1]), "r"(a[2]), "r"(a[3]), "r"(b0), "r"(b1));
}

__device__ __forceinline__ uint32_t mbit(uint2 mw, int k) {
    return ((k < 32 ? (mw.x >> k) : (mw.y >> (k - 32))) & 1u);
}

// ---------------------------------------------------------------------------
// pre-kernels
// ---------------------------------------------------------------------------
__global__ void vsum_kernel(const float* __restrict__ v) {
    int bh = blockIdx.x, tid = threadIdx.x;
    int d = tid & 63, strip = tid >> 6;
    const float* vp = v + (size_t)bh*SS_*DD;
    float acc = 0.f;
    for (int k = strip; k < SS_; k += 4) acc += vp[k*DD + d];
    __shared__ float red[4][64];
    red[strip][d] = acc;
    __syncthreads();
    if (strip == 0)
        g_vsum[bh*DD + d] = red[0][d] + red[1][d] + red[2][d] + red[3][d];
}

__global__ void maskpack_kernel(const int* __restrict__ m) {
    int i = blockIdx.x*256 + threadIdx.x;
    unsigned b = __ballot_sync(0xffffffffu, m[i] != 0);
    if ((threadIdx.x & 31) == 0) g_mbits[i >> 5] = b;
}

// ---------------------------------------------------------------------------
// main attention kernel: mma.sync tf32
//   out = (A1 - lse*A2) - 1e9*(A3 - A2)
//   A1 = sum_k m*s*v, A2 = sum_k m*v, lse = log sum_k exp(s), s = (q/8)·k
// ---------------------------------------------------------------------------
__global__ void __launch_bounds__(NT, 1)
attn_kernel(const float* __restrict__ gq, const float* __restrict__ gk,
            const float* __restrict__ gv, float* __restrict__ gout)
{
    extern __shared__ float sm[];
    float* Ks  = sm;                    // [64][KSTR]  tf32 bits
    float* Vs  = sm + 64*KSTR;          // [64][KSTR]  tf32 bits
    float* Sst = sm + 2*64*KSTR;        // [128][KSTR] raw fp32 scores
    uint32_t* Ksu = (uint32_t*)Ks;
    uint32_t* Vsu = (uint32_t*)Vs;
    __shared__ float vs_s[64];

    const int tid = threadIdx.x;
    const int w   = tid >> 5;           // warp 0..7: q rows [16w,16w+16)
    const int lane = tid & 31;
    const int g = lane >> 2;            // groupID
    const int t = lane & 3;             // thread-in-group
    const int bid = blockIdx.x;
    const int bh  = bid >> 4;
    const int qt  = bid & 15;
    const int qbase = qt * BQ;
    const int qlo = qbase + 16*w + g;   // this thread's low q row
    const int qhi = qlo + 8;

    if (tid < 64) vs_s[tid] = g_vsum[bh*DD + tid];

    // ---- persistent Q fragments (pre-scaled by 1/8, tf32-RN) ----
    uint32_t Qf[8][4];
    {
        const float* qp = gq + (size_t)bh*SS_*DD;
        #pragma unroll
        for (int c = 0; c < 8; c++) {
            Qf[c][0] = to_tf32(0.125f * qp[(size_t)qlo*DD + 8*c + t]);
            Qf[c][1] = to_tf32(0.125f * qp[(size_t)qhi*DD + 8*c + t]);
            Qf[c][2] = to_tf32(0.125f * qp[(size_t)qlo*DD + 8*c + t + 4]);
            Qf[c][3] = to_tf32(0.125f * qp[(size_t)qhi*DD + 8*c + t + 4]);
        }
    }

    const float* kbase = gk + (size_t)bh*SS_*DD;
    const float* vbase = gv + (size_t)bh*SS_*DD;
    const uint2* mrow_lo = (const uint2*)(g_mbits + (size_t)qlo*64);
    const uint2* mrow_hi = (const uint2*)(g_mbits + (size_t)qhi*64);

    float A1[8][4], A2[8][4];
    #pragma unroll
    for (int nb = 0; nb < 8; nb++)
        #pragma unroll
        for (int j = 0; j < 4; j++) { A1[nb][j] = 0.f; A2[nb][j] = 0.f; }
    float lsum_lo = 0.f, lsum_hi = 0.f;

    for (int kt = 0; kt < NKT; kt++) {
        __syncthreads();   // everyone done reading Ks/Vs from previous tile

        // ---- cooperative K,V tile loads (tf32-RN into SMEM) ----
        {
            const float* kp = kbase + (size_t)kt*BK*DD;
            const float* vp = vbase + (size_t)kt*BK*DD;
            #pragma unroll
            for (int i = 0; i < 16; i++) {
                int idx = tid + i*NT;
                int r = idx >> 6, col = idx & 63;
                Ksu[r*KSTR + col] = to_tf32(kp[idx]);
                Vsu[r*KSTR + col] = to_tf32(vp[idx]);
            }
        }
        __syncthreads();

        // ---- S = (Q/8) @ K^T, per warp 16x64 ----
        #pragma unroll
        for (int nb = 0; nb < 8; nb++) {
            float acc[4] = {0.f, 0.f, 0.f, 0.f};
            const uint32_t* kr = &Ksu[(8*nb + g)*KSTR];
            #pragma unroll
            for (int c = 0; c < 8; c++)
                mma8(acc, Qf[c], kr[8*c + t], kr[8*c + t + 4]);
            // accum layout: c0=(g,8nb+2t), c1=+1, c2=(g+8,8nb+2t), c3=+1
            *(float2*)&Sst[(16*w + g    )*KSTR + 8*nb + 2*t] = make_float2(acc[0], acc[1]);
            *(float2*)&Sst[(16*w + g + 8)*KSTR + 8*nb + 2*t] = make_float2(acc[2], acc[3]);
        }
        __syncwarp();      // Sst rows are warp-private: warp sync suffices

        // ---- PV: A1 += (m*s)@V, A2 += m@V; lse fused into s loads ----
        uint2 mwlo = mrow_lo[kt];
        uint2 mwhi = mrow_hi[kt];
        #pragma unroll
        for (int c = 0; c < 8; c++) {
            const int klo = 8*c + t, khi = klo + 4;
            float s0 = Sst[(16*w + g    )*KSTR + klo];
            float s1 = Sst[(16*w + g + 8)*KSTR + klo];
            float s2 = Sst[(16*w + g    )*KSTR + khi];
            float s3 = Sst[(16*w + g + 8)*KSTR + khi];
            lsum_lo += __expf(s0) + __expf(s2);
            lsum_hi += __expf(s1) + __expf(s3);
            uint32_t m0 = mbit(mwlo, klo), m1 = mbit(mwhi, klo);
            uint32_t m2 = mbit(mwlo, khi), m3 = mbit(mwhi, khi);
            uint32_t a1f[4], a2f[4];
            a1f[0] = m0 ? to_tf32(s0) : 0u;  a2f[0] = m0 ? 0x3f800000u : 0u;
            a1f[1] = m1 ? to_tf32(s1) : 0u;  a2f[1] = m1 ? 0x3f800000u : 0u;
            a1f[2] = m2 ? to_tf32(s2) : 0u;  a2f[2] = m2 ? 0x3f800000u : 0u;
            a1f[3] = m3 ? to_tf32(s3) : 0u;  a2f[3] = m3 ? 0x3f800000u : 0u;
            #pragma unroll
            for (int nb = 0; nb < 8; nb++) {
                uint32_t b0 = Vsu[klo*KSTR + 8*nb + g];
                uint32_t b1 = Vsu[khi*KSTR + 8*nb + g];
                mma8(A1[nb], a1f, b0, b1);
                mma8(A2[nb], a2f, b0, b1);
            }
        }
    }

    // ---- lse: reduce exp-sums across the 4 lanes of each group ----
    lsum_lo += __shfl_xor_sync(0xffffffffu, lsum_lo, 1);
    lsum_lo += __shfl_xor_sync(0xffffffffu, lsum_lo, 2);
    lsum_hi += __shfl_xor_sync(0xffffffffu, lsum_hi, 1);
    lsum_hi += __shfl_xor_sync(0xffffffffu, lsum_hi, 2);
    const float lse_lo = __logf(lsum_lo);
    const float lse_hi = __logf(lsum_hi);

    // ---- epilogue: out = (A1 - lse*A2) - 1e9*(vs - A2) ----
    __syncthreads();   // vs_s visible
    const int b = bh >> 4, h = bh & 15;
    float* olo = gout + ((size_t)b*SS_ + qlo)*(HH*DD) + h*DD;
    float* ohi = gout + ((size_t)b*SS_ + qhi)*(HH*DD) + h*DD;
    #pragma unroll
    for (int nb = 0; nb < 8; nb++) {
        int d = 8*nb + 2*t;
        float vs0 = vs_s[d], vs1 = vs_s[d + 1];
        float o0 = (A1[nb][0] - lse_lo*A2[nb][0]) - 1e9f*(vs0 - A2[nb][0]);
        float o1 = (A1[nb][1] - lse_lo*A2[nb][1]) - 1e9f*(vs1 - A2[nb][1]);
        float o2 = (A1[nb][2] - lse_hi*A2[nb][2]) - 1e9f*(vs0 - A2[nb][2]);
        float o3 = (A1[nb][3] - lse_hi*A2[nb][3]) - 1e9f*(vs1 - A2[nb][3]);
        *(float2*)&olo[d] = make_float2(o0, o1);
        *(float2*)&ohi[d] = make_float2(o2, o3);
    }
}

// ---------------------------------------------------------------------------
extern "C" void kernel_launch(void* const* d_in, const int* in_sizes, int n_in,
                              void* d_out, int out_size) {
    const float* q    = (const float*)d_in[0];
    const float* k    = (const float*)d_in[1];
    const float* v    = (const float*)d_in[2];
    const int*   mask = (const int*)d_in[3];
    float* out = (float*)d_out;

    const int dsm = (2*64*KSTR + 128*KSTR) * 4;   // 69632 bytes
    cudaFuncSetAttribute(attn_kernel,
                         cudaFuncAttributeMaxDynamicSharedMemorySize, dsm);

    maskpack_kernel<<<(SS_*SS_)/256, 256>>>(mask);
    vsum_kernel<<<NBH, 256>>>(v);
    attn_kernel<<<NBH*(SS_/BQ), NT, dsm>>>(q, k, v, out);
}

// round 5
// speedup vs baseline: 4.4547x; 1.4432x over previous
#include <cuda_runtime.h>
#include <cstdint>

#define BB 4
#define HH 16
#define SS_ 2048
#define DD 64
#define BQ 128
#define BK 64
#define NKT (SS_/BK)     /* 32 */
#define NBH (BB*HH)      /* 64 */
#define NT 256
#define VSTR 72          /* V float stride: lane bank = 8t+g (perfect) */
#define KSTRW 36         /* K bf16 stride in uint32 (= 72 halfs) */
#define SSTR 68          /* S float stride: lane bank = 4g+t (perfect) */

__device__ float    g_vsum[NBH*DD];
__device__ uint32_t g_mbits[SS_*(SS_/32)];

// ---------------- helpers ----------------
__device__ __forceinline__ uint32_t to_tf32(float f) {
    uint32_t r; asm("cvt.rn.tf32.f32 %0, %1;" : "=r"(r) : "f"(f)); return r;
}
__device__ __forceinline__ uint32_t bf2(float lo, float hi) {
    uint32_t r; asm("cvt.rn.bf16x2.f32 %0, %1, %2;" : "=r"(r) : "f"(hi), "f"(lo));
    return r;
}
// tf32: D += A(m16k8) * B(k8n8)
__device__ __forceinline__ void mma8(float* d, const uint32_t* a,
                                     uint32_t b0, uint32_t b1) {
    asm volatile(
        "mma.sync.aligned.m16n8k8.row.col.f32.tf32.tf32.f32 "
        "{%0,%1,%2,%3}, {%4,%5,%6,%7}, {%8,%9}, {%0,%1,%2,%3};"
        : "+f"(d[0]), "+f"(d[1]), "+f"(d[2]), "+f"(d[3])
        : "r"(a[0]), "r"(a[1]), "r"(a[2]), "r"(a[3]), "r"(b0), "r"(b1));
}
// bf16: D += A(m16k16) * B(k16n8)
__device__ __forceinline__ void mma16bf(float* d, const uint32_t* a,
                                        uint32_t b0, uint32_t b1) {
    asm volatile(
        "mma.sync.aligned.m16n8k16.row.col.f32.bf16.bf16.f32 "
        "{%0,%1,%2,%3}, {%4,%5,%6,%7}, {%8,%9}, {%0,%1,%2,%3};"
        : "+f"(d[0]), "+f"(d[1]), "+f"(d[2]), "+f"(d[3])
        : "r"(a[0]), "r"(a[1]), "r"(a[2]), "r"(a[3]), "r"(b0), "r"(b1));
}
__device__ __forceinline__ uint32_t mbit(uint2 mw, int k) {
    return ((k < 32 ? (mw.x >> k) : (mw.y >> (k - 32))) & 1u);
}

// ---------------------------------------------------------------------------
// pre-kernels
// ---------------------------------------------------------------------------
__global__ void vsum_kernel(const float* __restrict__ v) {
    int bh = blockIdx.x, tid = threadIdx.x;
    int d = tid & 63, strip = tid >> 6;
    const float* vp = v + (size_t)bh*SS_*DD;
    float a0 = 0.f, a1 = 0.f, a2 = 0.f, a3 = 0.f;
    for (int k = strip; k < SS_; k += 16) {
        a0 += vp[(k     )*DD + d];
        a1 += vp[(k +  4)*DD + d];
        a2 += vp[(k +  8)*DD + d];
        a3 += vp[(k + 12)*DD + d];
    }
    __shared__ float red[4][64];
    red[strip][d] = (a0 + a1) + (a2 + a3);
    __syncthreads();
    if (strip == 0)
        g_vsum[bh*DD + d] = red[0][d] + red[1][d] + red[2][d] + red[3][d];
}

__global__ void maskpack_kernel(const int* __restrict__ m) {
    int base = blockIdx.x*1024 + threadIdx.x;
    int a = m[base], b = m[base+256], c = m[base+512], d = m[base+768];
    unsigned ba = __ballot_sync(~0u, a != 0);
    unsigned bb = __ballot_sync(~0u, b != 0);
    unsigned bc = __ballot_sync(~0u, c != 0);
    unsigned bd = __ballot_sync(~0u, d != 0);
    if ((threadIdx.x & 31) == 0) {
        g_mbits[(base      ) >> 5] = ba;
        g_mbits[(base + 256) >> 5] = bb;
        g_mbits[(base + 512) >> 5] = bc;
        g_mbits[(base + 768) >> 5] = bd;
    }
}

// ---------------------------------------------------------------------------
// main attention kernel
//   out = (A1 - lse*A2) - 1e9*(A3 - A2)
//   S in bf16 mma, A1/A2 in tf32 mma (A2 carries the 1e9 term -> needs tf32-RN)
// ---------------------------------------------------------------------------
__global__ void __launch_bounds__(NT, 2)
attn_kernel(const float* __restrict__ gq, const float* __restrict__ gk,
            const float* __restrict__ gv, float* __restrict__ gout)
{
    extern __shared__ float sm[];
    uint32_t* Vsu = (uint32_t*)sm;                 // [64][VSTR]  tf32 bits
    uint32_t* Khu = (uint32_t*)(sm + 64*VSTR);     // [64][KSTRW] bf16x2
    float*    Sst = sm + 64*VSTR + 64*KSTRW;       // [128][SSTR] raw fp32 scores
    __shared__ float vs_s[64];

    const int tid = threadIdx.x;
    const int w   = tid >> 5;
    const int lane = tid & 31;
    const int g = lane >> 2;
    const int t = lane & 3;
    const int bid = blockIdx.x;
    const int bh  = bid >> 4;
    const int qt  = bid & 15;
    const int qbase = qt * BQ;
    const int qlo = qbase + 16*w + g;
    const int qhi = qlo + 8;

    if (tid < 64) vs_s[tid] = g_vsum[bh*DD + tid];

    // ---- persistent Q fragments: bf16 pairs, pre-scaled by 1/8 ----
    uint32_t Qf[4][4];
    {
        const float* ql = gq + (size_t)bh*SS_*DD + (size_t)qlo*DD;
        const float* qh = gq + (size_t)bh*SS_*DD + (size_t)qhi*DD;
        #pragma unroll
        for (int c4 = 0; c4 < 4; c4++) {
            int k0 = 16*c4 + 2*t;
            Qf[c4][0] = bf2(0.125f*ql[k0    ], 0.125f*ql[k0 + 1]);
            Qf[c4][1] = bf2(0.125f*qh[k0    ], 0.125f*qh[k0 + 1]);
            Qf[c4][2] = bf2(0.125f*ql[k0 + 8], 0.125f*ql[k0 + 9]);
            Qf[c4][3] = bf2(0.125f*qh[k0 + 8], 0.125f*qh[k0 + 9]);
        }
    }

    const float4* kbase4 = (const float4*)(gk + (size_t)bh*SS_*DD);
    const float4* vbase4 = (const float4*)(gv + (size_t)bh*SS_*DD);
    const uint2* mrow_lo = (const uint2*)(g_mbits + (size_t)qlo*64);
    const uint2* mrow_hi = (const uint2*)(g_mbits + (size_t)qhi*64);

    float A1[8][4], A2[8][4];
    #pragma unroll
    for (int nb = 0; nb < 8; nb++)
        #pragma unroll
        for (int j = 0; j < 4; j++) { A1[nb][j] = 0.f; A2[nb][j] = 0.f; }
    float lsum_lo = 0.f, lsum_hi = 0.f;

    for (int kt = 0; kt < NKT; kt++) {
        __syncthreads();   // previous tile fully consumed

        // ---- K tile -> bf16 smem, V tile -> tf32 smem (coalesced float4) ----
        #pragma unroll
        for (int i = 0; i < 4; i++) {
            int idx = tid + i*NT;          // 1024 float4 = 64x64 floats
            int r = idx >> 4, j = idx & 15;
            float4 kf = kbase4[(size_t)kt*1024 + idx];
            uint2 kb;
            kb.x = bf2(kf.x, kf.y);
            kb.y = bf2(kf.z, kf.w);
            *(uint2*)&Khu[r*KSTRW + 2*j] = kb;
            float4 vf = vbase4[(size_t)kt*1024 + idx];
            uint4 vb;
            vb.x = to_tf32(vf.x); vb.y = to_tf32(vf.y);
            vb.z = to_tf32(vf.z); vb.w = to_tf32(vf.w);
            *(uint4*)&Vsu[r*VSTR + 4*j] = vb;
        }
        __syncthreads();

        // ---- S = (Q/8) @ K^T : bf16 m16n8k16, per warp 16x64 ----
        #pragma unroll
        for (int nb = 0; nb < 8; nb++) {
            float acc[4] = {0.f, 0.f, 0.f, 0.f};
            const uint32_t* kr = &Khu[(8*nb + g)*KSTRW];
            #pragma unroll
            for (int c4 = 0; c4 < 4; c4++)
                mma16bf(acc, Qf[c4], kr[8*c4 + t], kr[8*c4 + t + 4]);
            *(float2*)&Sst[(16*w + g    )*SSTR + 8*nb + 2*t] = make_float2(acc[0], acc[1]);
            *(float2*)&Sst[(16*w + g + 8)*SSTR + 8*nb + 2*t] = make_float2(acc[2], acc[3]);
        }
        __syncwarp();      // Sst rows are warp-private

        // ---- PV: A1 += (m*s)@V, A2 += m@V; lse fused ----
        uint2 mwlo = mrow_lo[kt];
        uint2 mwhi = mrow_hi[kt];
        #pragma unroll
        for (int c = 0; c < 8; c++) {
            const int klo = 8*c + t, khi = klo + 4;
            float s0 = Sst[(16*w + g    )*SSTR + klo];
            float s1 = Sst[(16*w + g + 8)*SSTR + klo];
            float s2 = Sst[(16*w + g    )*SSTR + khi];
            float s3 = Sst[(16*w + g + 8)*SSTR + khi];
            lsum_lo += __expf(s0) + __expf(s2);
            lsum_hi += __expf(s1) + __expf(s3);
            uint32_t m0 = mbit(mwlo, klo), m1 = mbit(mwhi, klo);
            uint32_t m2 = mbit(mwlo, khi), m3 = mbit(mwhi, khi);
            uint32_t a1f[4], a2f[4];
            a1f[0] = m0 ? to_tf32(s0) : 0u;  a2f[0] = m0 ? 0x3f800000u : 0u;
            a1f[1] = m1 ? to_tf32(s1) : 0u;  a2f[1] = m1 ? 0x3f800000u : 0u;
            a1f[2] = m2 ? to_tf32(s2) : 0u;  a2f[2] = m2 ? 0x3f800000u : 0u;
            a1f[3] = m3 ? to_tf32(s3) : 0u;  a2f[3] = m3 ? 0x3f800000u : 0u;
            #pragma unroll
            for (int nb = 0; nb < 8; nb++) {
                uint32_t b0 = Vsu[klo*VSTR + 8*nb + g];
                uint32_t b1 = Vsu[khi*VSTR + 8*nb + g];
                mma8(A1[nb], a1f, b0, b1);
                mma8(A2[nb], a2f, b0, b1);
            }
        }
    }

    // ---- lse reduction within each 4-lane group ----
    lsum_lo += __shfl_xor_sync(0xffffffffu, lsum_lo, 1);
    lsum_lo += __shfl_xor_sync(0xffffffffu, lsum_lo, 2);
    lsum_hi += __shfl_xor_sync(0xffffffffu, lsum_hi, 1);
    lsum_hi += __shfl_xor_sync(0xffffffffu, lsum_hi, 2);
    const float lse_lo = __logf(lsum_lo);
    const float lse_hi = __logf(lsum_hi);

    // ---- epilogue ----
    __syncthreads();
    const int b = bh >> 4, h = bh & 15;
    float* olo = gout + ((size_t)b*SS_ + qlo)*(HH*DD) + h*DD;
    float* ohi = gout + ((size_t)b*SS_ + qhi)*(HH*DD) + h*DD;
    #pragma unroll
    for (int nb = 0; nb < 8; nb++) {
        int d = 8*nb + 2*t;
        float vs0 = vs_s[d], vs1 = vs_s[d + 1];
        float o0 = (A1[nb][0] - lse_lo*A2[nb][0]) - 1e9f*(vs0 - A2[nb][0]);
        float o1 = (A1[nb][1] - lse_lo*A2[nb][1]) - 1e9f*(vs1 - A2[nb][1]);
        float o2 = (A1[nb][2] - lse_hi*A2[nb][2]) - 1e9f*(vs0 - A2[nb][2]);
        float o3 = (A1[nb][3] - lse_hi*A2[nb][3]) - 1e9f*(vs1 - A2[nb][3]);
        *(float2*)&olo[d] = make_float2(o0, o1);
        *(float2*)&ohi[d] = make_float2(o2, o3);
    }
}

// ---------------------------------------------------------------------------
extern "C" void kernel_launch(void* const* d_in, const int* in_sizes, int n_in,
                              void* d_out, int out_size) {
    const float* q    = (const float*)d_in[0];
    const float* k    = (const float*)d_in[1];
    const float* v    = (const float*)d_in[2];
    const int*   mask = (const int*)d_in[3];
    float* out = (float*)d_out;

    const int dsm = (64*VSTR + 64*KSTRW + 128*SSTR) * 4;   // 62464 bytes
    cudaFuncSetAttribute(attn_kernel,
                         cudaFuncAttributeMaxDynamicSharedMemorySize, dsm);

    maskpack_kernel<<<(SS_*SS_)/1024, 256>>>(mask);
    vsum_kernel<<<NBH, 256>>>(v);
    attn_kernel<<<NBH*(SS_/BQ), NT, dsm>>>(q, k, v, out);
}